// round 4
// baseline (speedup 1.0000x reference)
#include <cuda_runtime.h>
#include <cuda_bf16.h>
#include <stdint.h>

// ============================================================================
// Problem constants
// ============================================================================
#define BA 8192
#define BB 16384
#define DIM 1024
#define LOSS_SCALE 20.0f

#define TM 128            // CTA rows
#define TN 128            // CTA cols per chunk
#define TKS 64            // K per pipeline stage
#define STAGES 4
#define NSPLIT 2          // column splits per row-block
#define CHUNKS (BB / NSPLIT / TN)     // 64 chunks of 128 cols per CTA
#define KSTAGES (DIM / TKS)           // 16 k-stages per chunk
#define TOTAL_STAGES (CHUNKS * KSTAGES)
#define ROWBLOCKS (BA / TM)           // 64
#define THREADS 256

// ============================================================================
// Device scratch
// ============================================================================
__device__ __nv_bfloat16 g_a_bf[(size_t)BA * DIM];   // 16 MB
__device__ __nv_bfloat16 g_b_bf[(size_t)BB * DIM];   // 32 MB
__device__ float g_inva[BA];
__device__ float g_invb[BB];
__device__ float g_pos[BA];
__device__ float g_pm[BA * NSPLIT];
__device__ float g_ps[BA * NSPLIT];
__device__ float g_part[ROWBLOCKS];

// ============================================================================
// SMEM layout (dynamic)
//   pitch per row = 72 bf16 = 144 B (conflict-free for ldmatrix, 16B aligned)
// ============================================================================
#define PITCH_B 144
#define STAGE_BYTES (128 * PITCH_B)          // 18432 per operand per stage
#define SM_A(stg) ((stg) * STAGE_BYTES)
#define SM_B(stg) (STAGES * STAGE_BYTES + (stg) * STAGE_BYTES)
#define SM_RED (2 * STAGES * STAGE_BYTES)               // float red[4][128][2]
#define SM_ROW (SM_RED + 4 * 128 * 2 * 4)               // float rowstate[128][2]
#define SMEM_TOTAL (SM_ROW + 128 * 2 * 4)

// ============================================================================
// PTX helpers
// ============================================================================
__device__ __forceinline__ uint32_t smem_to_u32(const void* p) {
    uint32_t a;
    asm("{ .reg .u64 t; cvta.to.shared.u64 t, %1; cvt.u32.u64 %0, t; }"
        : "=r"(a) : "l"(p));
    return a;
}

__device__ __forceinline__ void cp_async16(uint32_t s, const void* g) {
    asm volatile("cp.async.cg.shared.global [%0], [%1], 16;"
                 :: "r"(s), "l"(g) : "memory");
}
#define CP_COMMIT() asm volatile("cp.async.commit_group;" ::: "memory")
#define CP_WAIT(n)  asm volatile("cp.async.wait_group %0;" :: "n"(n) : "memory")

__device__ __forceinline__ void ldm_x4(uint32_t& r0, uint32_t& r1, uint32_t& r2,
                                       uint32_t& r3, uint32_t addr) {
    asm volatile("ldmatrix.sync.aligned.m8n8.x4.shared.b16 {%0,%1,%2,%3}, [%4];"
                 : "=r"(r0), "=r"(r1), "=r"(r2), "=r"(r3) : "r"(addr));
}
__device__ __forceinline__ void ldm_x2(uint32_t& r0, uint32_t& r1, uint32_t addr) {
    asm volatile("ldmatrix.sync.aligned.m8n8.x2.shared.b16 {%0,%1}, [%2];"
                 : "=r"(r0), "=r"(r1) : "r"(addr));
}

__device__ __forceinline__ void mma16816(float* c, uint32_t a0, uint32_t a1,
                                         uint32_t a2, uint32_t a3,
                                         uint32_t b0, uint32_t b1) {
    asm volatile(
        "mma.sync.aligned.m16n8k16.row.col.f32.bf16.bf16.f32 "
        "{%0,%1,%2,%3}, {%4,%5,%6,%7}, {%8,%9}, {%0,%1,%2,%3};"
        : "+f"(c[0]), "+f"(c[1]), "+f"(c[2]), "+f"(c[3])
        : "r"(a0), "r"(a1), "r"(a2), "r"(a3), "r"(b0), "r"(b1));
}

__device__ __forceinline__ void lse_merge(float& m, float& s, float om, float os) {
    float M = fmaxf(m, om);
    s = s * __expf(m - M) + os * __expf(om - M);
    m = M;
}

// ============================================================================
// Kernel 1: L2-normalize rows, write bf16 + inverse norms
// ============================================================================
__global__ void __launch_bounds__(128) normalize_kernel(const float* __restrict__ src, int which) {
    __nv_bfloat16* dst = which ? g_b_bf : g_a_bf;
    float* invn = which ? g_invb : g_inva;
    int row = blockIdx.x;
    int t = threadIdx.x;
    const float4* s4 = (const float4*)src + (size_t)row * (DIM / 4);
    float4 v0 = s4[t];
    float4 v1 = s4[t + 128];
    float ss = v0.x * v0.x + v0.y * v0.y + v0.z * v0.z + v0.w * v0.w
             + v1.x * v1.x + v1.y * v1.y + v1.z * v1.z + v1.w * v1.w;
    #pragma unroll
    for (int o = 16; o; o >>= 1) ss += __shfl_xor_sync(0xffffffffu, ss, o);
    __shared__ float ws[4];
    if ((t & 31) == 0) ws[t >> 5] = ss;
    __syncthreads();
    float inv = rsqrtf(ws[0] + ws[1] + ws[2] + ws[3]);
    if (t == 0) invn[row] = inv;
    __nv_bfloat162* d2 = (__nv_bfloat162*)dst + (size_t)row * (DIM / 2);
    d2[2 * t]           = __floats2bfloat162_rn(v0.x * inv, v0.y * inv);
    d2[2 * t + 1]       = __floats2bfloat162_rn(v0.z * inv, v0.w * inv);
    d2[256 + 2 * t]     = __floats2bfloat162_rn(v1.x * inv, v1.y * inv);
    d2[256 + 2 * t + 1] = __floats2bfloat162_rn(v1.z * inv, v1.w * inv);
}

// ============================================================================
// Kernel 2: positive logits (exact fp32)
// ============================================================================
__global__ void __launch_bounds__(128) pos_kernel(const float* __restrict__ a,
                                                  const float* __restrict__ b) {
    int row = blockIdx.x;
    int t = threadIdx.x;
    const float4* a4 = (const float4*)a + (size_t)row * (DIM / 4);
    const float4* b4 = (const float4*)b + (size_t)row * (DIM / 4);
    float4 x0 = a4[t], x1 = a4[t + 128];
    float4 y0 = b4[t], y1 = b4[t + 128];
    float acc = x0.x * y0.x + x0.y * y0.y + x0.z * y0.z + x0.w * y0.w
              + x1.x * y1.x + x1.y * y1.y + x1.z * y1.z + x1.w * y1.w;
    #pragma unroll
    for (int o = 16; o; o >>= 1) acc += __shfl_xor_sync(0xffffffffu, acc, o);
    __shared__ float ws[4];
    if ((t & 31) == 0) ws[t >> 5] = acc;
    __syncthreads();
    if (t == 0)
        g_pos[row] = LOSS_SCALE * (ws[0] + ws[1] + ws[2] + ws[3]) * g_inva[row] * g_invb[row];
}

// ============================================================================
// Kernel 3: fused GEMM (mma.sync bf16) + online row LSE
//   CTA: 128x128 tile, 256 threads, warp grid 2(m) x 4(n), warp tile 64x32.
// ============================================================================
__global__ void __launch_bounds__(THREADS, 1) gemm_lse_kernel() {
    extern __shared__ char sm[];
    uint32_t sb = smem_to_u32(sm);

    int t = threadIdx.x;
    int lane = t & 31;
    int w = t >> 5;
    int wm = w >> 2;             // 0..1
    int wn = w & 3;              // 0..3

    int rb = blockIdx.x / NSPLIT;
    int sp = blockIdx.x % NSPLIT;
    int col_base = sp * (BB / NSPLIT);

    float* red = (float*)(sm + SM_RED);          // [4][128][2]
    float* rowstate = (float*)(sm + SM_ROW);     // [128][2]
    if (t < 128) { rowstate[2 * t] = -1e30f; rowstate[2 * t + 1] = 0.f; }

    // per-thread cp.async chunk coords (4 chunks of 16B per operand per stage)
    // chunk id c = t + i*256 : row = c>>3 (0..127), seg = c&7 (16B each)
    const char* a_gbase = (const char*)(g_a_bf + (size_t)(rb * TM) * DIM);
    const char* b_gbase = (const char*)(g_b_bf + (size_t)col_base * DIM);

    float acc[4][4][4];
    #pragma unroll
    for (int mt = 0; mt < 4; mt++)
        #pragma unroll
        for (int nt = 0; nt < 4; nt++)
            #pragma unroll
            for (int j = 0; j < 4; j++) acc[mt][nt][j] = 0.f;

    // --- issue one pipeline stage's cp.asyncs ---
    auto issue = [&](int g) {
        if (g < TOTAL_STAGES) {
            int chunk = g >> 4;
            int kc = g & 15;
            int buf = g % STAGES;
            uint32_t sa = sb + SM_A(buf);
            uint32_t sbB = sb + SM_B(buf);
            size_t a_koff = (size_t)kc * (TKS * 2);
            size_t b_row0 = (size_t)chunk * TN;
            #pragma unroll
            for (int i = 0; i < 4; i++) {
                int c = t + i * 256;
                int row = c >> 3, seg = c & 7;
                cp_async16(sa + row * PITCH_B + seg * 16,
                           a_gbase + (size_t)row * (DIM * 2) + a_koff + seg * 16);
                cp_async16(sbB + row * PITCH_B + seg * 16,
                           b_gbase + (b_row0 + row) * (size_t)(DIM * 2) + a_koff + seg * 16);
            }
        }
        CP_COMMIT();
    };

    #pragma unroll
    for (int s = 0; s < STAGES - 1; s++) issue(s);

    for (int g = 0; g < TOTAL_STAGES; g++) {
        CP_WAIT(STAGES - 2);
        __syncthreads();
        issue(g + STAGES - 1);

        int buf = g % STAGES;
        uint32_t sa = sb + SM_A(buf) + (uint32_t)(wm * 64 + (lane & 15)) * PITCH_B
                    + ((lane >> 4) * 16);
        uint32_t sbb = sb + SM_B(buf) + (uint32_t)(wn * 32 + (lane & 7)) * PITCH_B
                     + (((lane >> 3) & 1) * 16);

        #pragma unroll
        for (int kk = 0; kk < 4; kk++) {
            uint32_t a0[4], a1[4], a2[4], a3[4];
            uint32_t b0[4], b1[4];
            #pragma unroll
            for (int mt = 0; mt < 4; mt++)
                ldm_x4(a0[mt], a1[mt], a2[mt], a3[mt],
                       sa + mt * 16 * PITCH_B + kk * 32);
            #pragma unroll
            for (int nt = 0; nt < 4; nt++)
                ldm_x2(b0[nt], b1[nt], sbb + nt * 8 * PITCH_B + kk * 32);
            #pragma unroll
            for (int mt = 0; mt < 4; mt++)
                #pragma unroll
                for (int nt = 0; nt < 4; nt++)
                    mma16816(acc[mt][nt], a0[mt], a1[mt], a2[mt], a3[mt],
                             b0[nt], b1[nt]);
        }

        if ((g & 15) == 15) {
            // ---- flash-LSE epilogue for this 128-col chunk ----
            #pragma unroll
            for (int mt = 0; mt < 4; mt++) {
                #pragma unroll
                for (int h = 0; h < 2; h++) {
                    float m = -1e30f;
                    #pragma unroll
                    for (int nt = 0; nt < 4; nt++) {
                        m = fmaxf(m, acc[mt][nt][2 * h]);
                        m = fmaxf(m, acc[mt][nt][2 * h + 1]);
                    }
                    m *= LOSS_SCALE;
                    float s = 0.f;
                    #pragma unroll
                    for (int nt = 0; nt < 4; nt++) {
                        s += __expf(LOSS_SCALE * acc[mt][nt][2 * h] - m);
                        s += __expf(LOSS_SCALE * acc[mt][nt][2 * h + 1] - m);
                    }
                    // quad reduce (lanes sharing the same row: xor 1, 2)
                    #pragma unroll
                    for (int off = 1; off <= 2; off <<= 1) {
                        float om = __shfl_xor_sync(0xffffffffu, m, off);
                        float os = __shfl_xor_sync(0xffffffffu, s, off);
                        lse_merge(m, s, om, os);
                    }
                    if ((lane & 3) == 0) {
                        int row = wm * 64 + mt * 16 + h * 8 + (lane >> 2);
                        red[(wn * 128 + row) * 2] = m;
                        red[(wn * 128 + row) * 2 + 1] = s;
                    }
                    #pragma unroll
                    for (int nt = 0; nt < 4; nt++) {
                        acc[mt][nt][2 * h] = 0.f;
                        acc[mt][nt][2 * h + 1] = 0.f;
                    }
                }
            }
            __syncthreads();
            if (t < 128) {
                float m = rowstate[2 * t], s = rowstate[2 * t + 1];
                #pragma unroll
                for (int cw = 0; cw < 4; cw++)
                    lse_merge(m, s, red[(cw * 128 + t) * 2], red[(cw * 128 + t) * 2 + 1]);
                rowstate[2 * t] = m;
                rowstate[2 * t + 1] = s;
            }
            // next loop iteration's __syncthreads orders red reuse
        }
    }

    __syncthreads();
    if (t < 128) {
        int row_g = rb * TM + t;
        g_pm[row_g * NSPLIT + sp] = rowstate[2 * t];
        g_ps[row_g * NSPLIT + sp] = rowstate[2 * t + 1];
    }
}

// ============================================================================
// Kernel 4/5: deterministic LSE combine + mean
// ============================================================================
__global__ void __launch_bounds__(128) combine_kernel() {
    int row = blockIdx.x * 128 + threadIdx.x;
    float M = -1e30f;
    float mv[NSPLIT], sv[NSPLIT];
    #pragma unroll
    for (int sp = 0; sp < NSPLIT; sp++) {
        mv[sp] = g_pm[row * NSPLIT + sp];
        sv[sp] = g_ps[row * NSPLIT + sp];
        M = fmaxf(M, mv[sp]);
    }
    float S = 0.f;
    #pragma unroll
    for (int sp = 0; sp < NSPLIT; sp++) S += sv[sp] * __expf(mv[sp] - M);
    float li = M + logf(S) - g_pos[row];
    #pragma unroll
    for (int o = 16; o; o >>= 1) li += __shfl_xor_sync(0xffffffffu, li, o);
    __shared__ float ws[4];
    if ((threadIdx.x & 31) == 0) ws[threadIdx.x >> 5] = li;
    __syncthreads();
    if (threadIdx.x == 0) g_part[blockIdx.x] = ws[0] + ws[1] + ws[2] + ws[3];
}

__global__ void __launch_bounds__(64) final_kernel(float* __restrict__ out) {
    float v = g_part[threadIdx.x];
    #pragma unroll
    for (int o = 16; o; o >>= 1) v += __shfl_xor_sync(0xffffffffu, v, o);
    __shared__ float ws[2];
    if ((threadIdx.x & 31) == 0) ws[threadIdx.x >> 5] = v;
    __syncthreads();
    if (threadIdx.x == 0) out[0] = (ws[0] + ws[1]) * (1.0f / (float)BA);
}

// ============================================================================
// Launch
// ============================================================================
extern "C" void kernel_launch(void* const* d_in, const int* in_sizes, int n_in,
                              void* d_out, int out_size) {
    (void)in_sizes; (void)n_in; (void)out_size;
    const float* a = (const float*)d_in[0];
    const float* b = (const float*)d_in[1];
    float* out = (float*)d_out;

    cudaFuncSetAttribute(gemm_lse_kernel,
                         cudaFuncAttributeMaxDynamicSharedMemorySize, SMEM_TOTAL);

    normalize_kernel<<<BA, 128>>>(a, 0);
    normalize_kernel<<<BB, 128>>>(b, 1);
    pos_kernel<<<BA, 128>>>(a, b);
    gemm_lse_kernel<<<ROWBLOCKS * NSPLIT, THREADS, SMEM_TOTAL>>>();
    combine_kernel<<<ROWBLOCKS, 128>>>();
    final_kernel<<<1, 64>>>(out);
}